// round 16
// baseline (speedup 1.0000x reference)
#include <cuda_runtime.h>
#include <math_constants.h>

#define N 512
#define D 128
#define MARGIN 0.3f
#define TS 32
#define KS 130          // padded smem row stride (bank stride 2 -> conflict-free float2)
#define NTILES 136      // triangular 32x32 tiles

__device__ float    g_Dm[N * N];     // pairwise distances
__device__ float    g_psum[N];       // per-block partial sums (slot per block)
__device__ unsigned g_pcnt[N];       // per-block partial counts
__device__ unsigned g_flag[N];       // slot-ready flags (reset by reducer)

// ---------------------------------------------------------------------------
// K1: pairwise distances via norm trick (pure FFMA inner loop), triangular
// tiles + mirror store. 136 blocks x 256 threads, 2x2 micro-tile. (Proven.)
// ---------------------------------------------------------------------------
__global__ __launch_bounds__(256)
void dist_kernel(const float* __restrict__ X) {
    __shared__ __align__(16) float As[TS * KS];
    __shared__ __align__(16) float Bs[TS * KS];
    __shared__ float nrm[64];

    const int tid  = threadIdx.x;
    const int lane = tid & 31;
    const int warp = tid >> 5;
    const int b    = blockIdx.x;

    int ti = (int)((sqrtf(8.0f * (float)b + 1.0f) - 1.0f) * 0.5f);
    while ((ti + 1) * (ti + 2) / 2 <= b) ti++;
    while (ti * (ti + 1) / 2 > b) ti--;
    const int tj = b - ti * (ti + 1) / 2;
    const int i0 = ti * TS, j0 = tj * TS;

    const float2* __restrict__ X2 = (const float2*)X;
    #pragma unroll
    for (int v = 0; v < 8; v++) {
        const int idx = tid + v * 256;
        const int r = idx >> 6, c = idx & 63;
        ((float2*)(As + r * KS))[c] = X2[(i0 + r) * (D / 2) + c];
        ((float2*)(Bs + r * KS))[c] = X2[(j0 + r) * (D / 2) + c];
    }
    __syncthreads();

    #pragma unroll
    for (int r8 = 0; r8 < 8; r8++) {
        const int row = warp * 8 + r8;
        const float* src = (row < 32) ? (As + row * KS) : (Bs + (row - 32) * KS);
        const float2 v0 = ((const float2*)src)[lane];
        const float2 v1 = ((const float2*)src)[lane + 32];
        float s = v0.x * v0.x + v0.y * v0.y + v1.x * v1.x + v1.y * v1.y;
        #pragma unroll
        for (int o = 16; o > 0; o >>= 1)
            s += __shfl_xor_sync(0xffffffffu, s, o);
        if (lane == 0) nrm[row] = s;
    }
    __syncthreads();

    const int tx = tid & 15, ty = tid >> 4;
    const float* a0p = As + ty * KS;
    const float* a1p = As + (ty + 16) * KS;
    const float* b0p = Bs + tx * KS;
    const float* b1p = Bs + (tx + 16) * KS;

    float c00 = 0.f, c01 = 0.f, c10 = 0.f, c11 = 0.f;
    #pragma unroll 16
    for (int k = 0; k < D; k += 2) {
        const float2 a0 = *(const float2*)(a0p + k);
        const float2 a1 = *(const float2*)(a1p + k);
        const float2 b0 = *(const float2*)(b0p + k);
        const float2 b1 = *(const float2*)(b1p + k);
        c00 += a0.x * b0.x; c00 += a0.y * b0.y;
        c01 += a0.x * b1.x; c01 += a0.y * b1.y;
        c10 += a1.x * b0.x; c10 += a1.y * b0.y;
        c11 += a1.x * b1.x; c11 += a1.y * b1.y;
    }

    const float na0 = nrm[ty], na1 = nrm[ty + 16];
    const float nb0 = nrm[32 + tx], nb1 = nrm[32 + tx + 16];
    const float d00 = sqrtf(fmaxf(na0 + nb0 - 2.0f * c00, 0.0f));
    const float d01 = sqrtf(fmaxf(na0 + nb1 - 2.0f * c01, 0.0f));
    const float d10 = sqrtf(fmaxf(na1 + nb0 - 2.0f * c10, 0.0f));
    const float d11 = sqrtf(fmaxf(na1 + nb1 - 2.0f * c11, 0.0f));

    const int gi0 = i0 + ty, gi1 = i0 + ty + 16;
    const int gj0 = j0 + tx, gj1 = j0 + tx + 16;
    g_Dm[gi0 * N + gj0] = d00;
    g_Dm[gi0 * N + gj1] = d01;
    g_Dm[gi1 * N + gj0] = d10;
    g_Dm[gi1 * N + gj1] = d11;
    if (ti != tj) {
        g_Dm[gj0 * N + gi0] = d00;
        g_Dm[gj1 * N + gi0] = d01;
        g_Dm[gj0 * N + gi1] = d10;
        g_Dm[gj1 * N + gi1] = d11;
    }
}

// ---------------------------------------------------------------------------
// K2: block-per-anchor (R4's proven interior) + SLOT finalize: distinct-slot
// stores + flag, block 0 polls & reduces. NO same-address atomic chains.
// ---------------------------------------------------------------------------
__global__ __launch_bounds__(256)
void triplet_kernel(const int* __restrict__ labels, float* __restrict__ out) {
    __shared__ float posA[64];
    __shared__ int   npos;
    __shared__ float wsum[8];
    __shared__ int   wcnt[8];
    __shared__ float ownS;
    __shared__ int   ownC;

    const int tid  = threadIdx.x;
    const int lane = tid & 31;
    const int warp = tid >> 5;
    const int i    = blockIdx.x;           // anchor

    if (tid == 0) npos = 0;
    const int li = __ldg(&labels[i]);
    __syncthreads();

    // Each thread owns 2 (dist, label) pairs of row i, coalesced.
    float dn[2];
    #pragma unroll
    for (int v = 0; v < 2; v++) {
        const int k = tid + v * 256;
        const float dv = g_Dm[i * N + k];
        const int   lb = __ldg(&labels[k]);
        const bool isPos = (lb == li) && (k != i);
        if (isPos) {
            const int s = atomicAdd(&npos, 1);   // smem, rare (~10/block)
            if (s < 64) posA[s] = dv + MARGIN;
        }
        dn[v] = (lb != li) ? dv : CUDART_INF_F;  // masked -> relu & count 0
    }
    __syncthreads();

    int np = npos;
    if (np > 64) np = 64;

    float lsum = 0.0f;
    int   lcnt = 0;
    for (int p = 0; p < np; p++) {
        const float A = posA[p];                 // broadcast LDS
        #pragma unroll
        for (int v = 0; v < 2; v++) {
            const float t = A - dn[v];
            if (t > 0.0f)    lsum += t;
            if (t > 1e-16f)  lcnt += 1;
        }
    }

    #pragma unroll
    for (int o = 16; o > 0; o >>= 1) {
        lsum += __shfl_xor_sync(0xffffffffu, lsum, o);
        lcnt += __shfl_xor_sync(0xffffffffu, lcnt, o);
    }
    if (lane == 0) { wsum[warp] = lsum; wcnt[warp] = lcnt; }
    __syncthreads();

    if (tid == 0) {
        float s = 0.0f; int c = 0;
        #pragma unroll
        for (int w = 0; w < 8; w++) { s += wsum[w]; c += wcnt[w]; }
        if (i != 0) {
            // distinct slots: no contention, no RMW, fire-and-forget
            volatile float*    vs = g_psum;
            volatile unsigned* vc = g_pcnt;
            volatile unsigned* vf = g_flag;
            vs[i] = s;
            vc[i] = (unsigned)c;
            __threadfence();                     // payload before flag
            vf[i] = 1u;
        } else {
            ownS = s; ownC = c;
        }
    }

    // ---- Block 0: poll slots 1..511 (pure loads), reduce, write scalar.
    if (i == 0) {
        __syncthreads();
        volatile float*    vs = g_psum;
        volatile unsigned* vc = g_pcnt;
        volatile unsigned* vf = g_flag;

        const int s0 = 1 + tid;                  // 1..256
        const int s1 = 257 + tid;                // 257..512 (skip >= 512)
        while (vf[s0] == 0u) __nanosleep(64);
        if (s1 < N) { while (vf[s1] == 0u) __nanosleep(64); }
        __threadfence();                         // flags before payload reads

        float fs = vs[s0];
        int   fc = (int)vc[s0];
        vf[s0] = 0u;                             // reset for next replay
        if (s1 < N) {
            fs += vs[s1];
            fc += (int)vc[s1];
            vf[s1] = 0u;
        }
        __syncthreads();                         // all payloads consumed

        #pragma unroll
        for (int o = 16; o > 0; o >>= 1) {
            fs += __shfl_xor_sync(0xffffffffu, fs, o);
            fc += __shfl_xor_sync(0xffffffffu, fc, o);
        }
        if (lane == 0) { wsum[warp] = fs; wcnt[warp] = fc; }
        __syncthreads();
        if (tid == 0) {
            double S = (double)ownS;
            long long C = (long long)ownC;
            #pragma unroll
            for (int w = 0; w < 8; w++) { S += (double)wsum[w]; C += wcnt[w]; }
            out[0] = (float)(S / ((double)C + 1e-16));
        }
    }
}

extern "C" void kernel_launch(void* const* d_in, const int* in_sizes, int n_in,
                              void* d_out, int out_size) {
    const float* X      = (const float*)d_in[0];   // [512, 128] fp32
    const int*   labels = (const int*)d_in[1];     // [512] int32
    float*       out    = (float*)d_out;           // scalar fp32

    dist_kernel<<<NTILES, 256>>>(X);
    triplet_kernel<<<N, 256>>>(labels, out);
}